// round 1
// baseline (speedup 1.0000x reference)
#include <cuda_runtime.h>

#define S 384
#define D 512
#define H 8
#define DK 64
#define OUT_MAIN (S*S*D)   // 75497472

// ---------------- scratch (device globals; no allocs allowed) ----------------
__device__ float g_q[S*D];
__device__ float g_k[S*D];
__device__ float g_v[S*D];
__device__ float g_M[H*DK*DK];     // M_h = Wq_h @ Wk_h^T
__device__ float g_Wvo[DK*D];      // Wv_s @ Wo
__device__ float g_bvo[D];         // bv_s @ Wo
__device__ float g_wh[H*DK];       // Wk_h[h] @ bq_h[h]
__device__ float g_qp[H*S*DK];     // q' = qr @ M_h
__device__ float g_bt[H*S];        // b-term per (h,t)
__device__ float g_hvo[H*S*D];     // (vr@Wvo + bvo)
__device__ float g_attn[H*S*S];    // softmax result

// ---------------- K1a: M_h[h,i,j] = sum_d Wq_h[h,i,d]*Wk_h[h,j,d] ----------------
__global__ __launch_bounds__(256) void k_pre_M(const float* __restrict__ Wqh,
                                               const float* __restrict__ Wkh) {
    int h = blockIdx.x, i0 = blockIdx.y * 32, j0 = blockIdx.z * 32;
    __shared__ float sA[32][33];
    __shared__ float sB[32][33];
    int ii = threadIdx.x >> 3;
    int j4 = (threadIdx.x & 7) * 4;
    const float* A = Wqh + h * DK * D;
    const float* Bm = Wkh + h * DK * D;
    float acc[4] = {0.f, 0.f, 0.f, 0.f};
    int r = threadIdx.x >> 3, c4 = (threadIdx.x & 7) * 4;
    for (int d0 = 0; d0 < D; d0 += 32) {
        float4 a4 = *(const float4*)(A + (i0 + r) * D + d0 + c4);
        sA[r][c4] = a4.x; sA[r][c4+1] = a4.y; sA[r][c4+2] = a4.z; sA[r][c4+3] = a4.w;
        float4 b4 = *(const float4*)(Bm + (j0 + r) * D + d0 + c4);
        sB[r][c4] = b4.x; sB[r][c4+1] = b4.y; sB[r][c4+2] = b4.z; sB[r][c4+3] = b4.w;
        __syncthreads();
        #pragma unroll
        for (int dd = 0; dd < 32; dd++) {
            float a = sA[ii][dd];
            #pragma unroll
            for (int q = 0; q < 4; q++) acc[q] += a * sB[j4 + q][dd];
        }
        __syncthreads();
    }
    #pragma unroll
    for (int q = 0; q < 4; q++)
        g_M[h * DK * DK + (i0 + ii) * DK + (j0 + j4 + q)] = acc[q];
}

// ---------------- K1b: Wvo = Wv_s[64,512] @ Wo[512,512] ----------------
__global__ __launch_bounds__(256) void k_pre_wvo(const float* __restrict__ Wvs,
                                                 const float* __restrict__ Wo) {
    int n0 = blockIdx.x * 64, m0 = blockIdx.y * 32;
    __shared__ float sA[32][33];   // [m][k]
    __shared__ float sB[32][64];   // [k][n]
    int i = threadIdx.x & 31;
    int g = threadIdx.x >> 5;
    float acc[8] = {};
    int ra = threadIdx.x >> 3, ca = (threadIdx.x & 7) * 4;
    int rb = threadIdx.x >> 3, cb = (threadIdx.x & 7) * 8;
    for (int k0 = 0; k0 < D; k0 += 32) {
        float4 a4 = *(const float4*)(Wvs + (m0 + ra) * D + k0 + ca);
        sA[ra][ca] = a4.x; sA[ra][ca+1] = a4.y; sA[ra][ca+2] = a4.z; sA[ra][ca+3] = a4.w;
        float4 b0 = *(const float4*)(Wo + (k0 + rb) * D + n0 + cb);
        float4 b1 = *(const float4*)(Wo + (k0 + rb) * D + n0 + cb + 4);
        sB[rb][cb]   = b0.x; sB[rb][cb+1] = b0.y; sB[rb][cb+2] = b0.z; sB[rb][cb+3] = b0.w;
        sB[rb][cb+4] = b1.x; sB[rb][cb+5] = b1.y; sB[rb][cb+6] = b1.z; sB[rb][cb+7] = b1.w;
        __syncthreads();
        #pragma unroll
        for (int kk = 0; kk < 32; kk++) {
            float a = sA[i][kk];
            #pragma unroll
            for (int q = 0; q < 8; q++) acc[q] += a * sB[kk][g * 8 + q];
        }
        __syncthreads();
    }
    #pragma unroll
    for (int q = 0; q < 8; q++)
        g_Wvo[(m0 + i) * D + n0 + g * 8 + q] = acc[q];
}

// ---------------- K1c: bvo = bv_s @ Wo ; wh[h] = Wk_h[h] @ bq_h[h] ----------------
__global__ __launch_bounds__(512) void k_pre_small(const float* __restrict__ Wo,
                                                   const float* __restrict__ bvs,
                                                   const float* __restrict__ Wkh,
                                                   const float* __restrict__ bqh) {
    if (blockIdx.x == 0) {
        int n = threadIdx.x;
        float acc = 0.f;
        for (int k = 0; k < D; k++) acc += bvs[k] * Wo[k * D + n];
        g_bvo[n] = acc;
    } else {
        int h = threadIdx.x >> 6, i = threadIdx.x & 63;
        const float* w = Wkh + (h * DK + i) * D;
        const float* b = bqh + h * D;
        float acc = 0.f;
        for (int d = 0; d < D; d++) acc += w[d] * b[d];
        g_wh[h * DK + i] = acc;
    }
}

// ---------------- K2: q,k,v = x @ {Wq,Wk,Wv} + bias ----------------
__global__ __launch_bounds__(256) void k_qkv(const float* __restrict__ x,
                                             const float* __restrict__ Wq, const float* __restrict__ bq,
                                             const float* __restrict__ Wk, const float* __restrict__ bk,
                                             const float* __restrict__ Wv, const float* __restrict__ bv) {
    const float* W; const float* bias; float* out;
    if (blockIdx.z == 0)      { W = Wq; bias = bq; out = g_q; }
    else if (blockIdx.z == 1) { W = Wk; bias = bk; out = g_k; }
    else                      { W = Wv; bias = bv; out = g_v; }
    int m0 = blockIdx.x * 64, n0 = blockIdx.y * 64;
    __shared__ float sA[16][68];  // [k][m]
    __shared__ float sB[16][68];  // [k][n]
    int tm = (threadIdx.x >> 4) * 4;
    int tn = (threadIdx.x & 15) * 4;
    float acc[4][4] = {};
    int mm = threadIdx.x >> 2, kk4 = (threadIdx.x & 3) * 4;
    int kk = threadIdx.x >> 4, nn4 = (threadIdx.x & 15) * 4;
    for (int k0 = 0; k0 < D; k0 += 16) {
        float4 a = *(const float4*)(x + (m0 + mm) * D + k0 + kk4);
        sA[kk4][mm] = a.x; sA[kk4+1][mm] = a.y; sA[kk4+2][mm] = a.z; sA[kk4+3][mm] = a.w;
        float4 b = *(const float4*)(W + (k0 + kk) * D + n0 + nn4);
        sB[kk][nn4] = b.x; sB[kk][nn4+1] = b.y; sB[kk][nn4+2] = b.z; sB[kk][nn4+3] = b.w;
        __syncthreads();
        #pragma unroll
        for (int k2 = 0; k2 < 16; k2++) {
            float av[4], bv4[4];
            #pragma unroll
            for (int i = 0; i < 4; i++) { av[i] = sA[k2][tm + i]; bv4[i] = sB[k2][tn + i]; }
            #pragma unroll
            for (int i = 0; i < 4; i++)
                #pragma unroll
                for (int j = 0; j < 4; j++) acc[i][j] += av[i] * bv4[j];
        }
        __syncthreads();
    }
    #pragma unroll
    for (int i = 0; i < 4; i++)
        #pragma unroll
        for (int j = 0; j < 4; j++)
            out[(m0 + tm + i) * D + n0 + tn + j] = acc[i][j] + bias[n0 + tn + j];
}

// ---------------- K3a: q'[h,s,:] = qr[s,h,:] @ M_h ----------------
__global__ __launch_bounds__(256) void k_qprime() {
    int h = blockIdx.x, s0 = blockIdx.y * 64;
    __shared__ float sM[64][65];
    __shared__ float sQ[64][65];
    #pragma unroll
    for (int r = 0; r < 4; r++) {
        int lin = threadIdx.x * 4 + r * 1024;
        int row = lin >> 6, col = lin & 63;
        float4 m4 = *(const float4*)(g_M + h * DK * DK + lin);
        sM[row][col] = m4.x; sM[row][col+1] = m4.y; sM[row][col+2] = m4.z; sM[row][col+3] = m4.w;
        float4 q4 = *(const float4*)(g_q + (s0 + row) * D + h * DK + col);
        sQ[row][col] = q4.x; sQ[row][col+1] = q4.y; sQ[row][col+2] = q4.z; sQ[row][col+3] = q4.w;
    }
    __syncthreads();
    int sl = threadIdx.x >> 2, jg = (threadIdx.x & 3) * 16;
    float acc[16] = {};
    #pragma unroll
    for (int i = 0; i < 64; i++) {
        float qv = sQ[sl][i];
        #pragma unroll
        for (int r = 0; r < 16; r++) acc[r] += qv * sM[i][jg + r];
    }
    #pragma unroll
    for (int r = 0; r < 16; r++)
        g_qp[(h * S + s0 + sl) * DK + jg + r] = acc[r];
}

// ---------------- K3b: hvo[h,t,:] = vr[t,h,:] @ Wvo + bvo ----------------
__global__ __launch_bounds__(256) void k_hvo() {
    int n0 = blockIdx.x * 64;
    int h = blockIdx.y / 6, t0 = (blockIdx.y % 6) * 64;
    __shared__ float sV[64][65];  // [t][i]
    __shared__ float sW[64][65];  // [i][n]
    #pragma unroll
    for (int r = 0; r < 4; r++) {
        int lin = threadIdx.x * 4 + r * 1024;
        int row = lin >> 6, col = lin & 63;
        float4 v4 = *(const float4*)(g_v + (t0 + row) * D + h * DK + col);
        sV[row][col] = v4.x; sV[row][col+1] = v4.y; sV[row][col+2] = v4.z; sV[row][col+3] = v4.w;
        float4 w4 = *(const float4*)(g_Wvo + row * D + n0 + col);
        sW[row][col] = w4.x; sW[row][col+1] = w4.y; sW[row][col+2] = w4.z; sW[row][col+3] = w4.w;
    }
    __syncthreads();
    int tl = threadIdx.x >> 2, ng = (threadIdx.x & 3) * 16;
    float acc[16];
    #pragma unroll
    for (int r = 0; r < 16; r++) acc[r] = g_bvo[n0 + ng + r];
    #pragma unroll
    for (int i = 0; i < 64; i++) {
        float vv = sV[tl][i];
        #pragma unroll
        for (int r = 0; r < 16; r++) acc[r] += vv * sW[i][ng + r];
    }
    #pragma unroll
    for (int r = 0; r < 16; r++)
        g_hvo[(h * S + t0 + tl) * D + n0 + ng + r] = acc[r];
}

// ---------------- K3c: b-term[h,t] = kr[t,h,:] . wh[h] ----------------
__global__ __launch_bounds__(256) void k_bterm() {
    int id = blockIdx.x * 256 + threadIdx.x;   // 3072 = H*S
    int h = id / S, t = id % S;
    const float4* kp = (const float4*)(g_k + t * D + h * DK);
    const float4* wp = (const float4*)(g_wh + h * DK);
    float acc = 0.f;
    #pragma unroll
    for (int i = 0; i < 16; i++) {
        float4 k4 = kp[i], w4 = wp[i];
        acc += k4.x * w4.x + k4.y * w4.y + k4.z * w4.z + k4.w * w4.w;
    }
    g_bt[h * S + t] = acc;
}

// ---------------- K4: scores + softmax, per (h,s) row ----------------
__global__ __launch_bounds__(128) void k_attn(float* __restrict__ d_out, long long out_size) {
    int s = blockIdx.x, h = blockIdx.y;
    __shared__ float sQp[64];
    __shared__ float red[4];
    int tid = threadIdx.x;
    if (tid < 64) sQp[tid] = g_qp[(h * S + s) * DK + tid];
    __syncthreads();
    float sc[3];
    #pragma unroll
    for (int r = 0; r < 3; r++) {
        int t = tid + r * 128;
        const float4* kp = (const float4*)(g_k + t * D + h * DK);
        float acc = 0.f;
        #pragma unroll
        for (int i = 0; i < 16; i++) {
            float4 k4 = kp[i];
            acc += sQp[i*4] * k4.x + sQp[i*4+1] * k4.y + sQp[i*4+2] * k4.z + sQp[i*4+3] * k4.w;
        }
        sc[r] = (acc + g_bt[h * S + t]) * 0.125f;
    }
    float mx = fmaxf(sc[0], fmaxf(sc[1], sc[2]));
    #pragma unroll
    for (int o = 16; o; o >>= 1) mx = fmaxf(mx, __shfl_xor_sync(0xffffffffu, mx, o));
    if ((tid & 31) == 0) red[tid >> 5] = mx;
    __syncthreads();
    mx = fmaxf(fmaxf(red[0], red[1]), fmaxf(red[2], red[3]));
    __syncthreads();
    float e[3], sum = 0.f;
    #pragma unroll
    for (int r = 0; r < 3; r++) { e[r] = __expf(sc[r] - mx); sum += e[r]; }
    #pragma unroll
    for (int o = 16; o; o >>= 1) sum += __shfl_xor_sync(0xffffffffu, sum, o);
    if ((tid & 31) == 0) red[tid >> 5] = sum;
    __syncthreads();
    float inv = 1.0f / (red[0] + red[1] + red[2] + red[3]);
    #pragma unroll
    for (int r = 0; r < 3; r++) {
        int t = tid + r * 128;
        float a = e[r] * inv;
        g_attn[(h * S + s) * S + t] = a;
        if (h == H - 1) {
            long long oi = (long long)OUT_MAIN + (long long)s * S + t;
            if (oi < out_size) d_out[oi] = a;
        }
    }
}

// ---------------- K5: out[s,t,:] = bo + (1/H) * sum_h attn[h,s,t] * hvo[h,t,:] ----------------
__global__ __launch_bounds__(128) void k_comb(float* __restrict__ d_out,
                                              const float* __restrict__ bo,
                                              long long out_size) {
    int t = blockIdx.x;
    int s0 = blockIdx.y * 48;
    int d4 = threadIdx.x * 4;
    float4 hv[H];
    #pragma unroll
    for (int h = 0; h < H; h++) {
        float4 v = *(const float4*)(g_hvo + (h * S + t) * D + d4);
        v.x *= 0.125f; v.y *= 0.125f; v.z *= 0.125f; v.w *= 0.125f;
        hv[h] = v;
    }
    float4 b4 = *(const float4*)(bo + d4);
    for (int si = 0; si < 48; si++) {
        int s = s0 + si;
        float w[H];
        #pragma unroll
        for (int h = 0; h < H; h++) w[h] = __ldg(g_attn + (h * S + s) * S + t);
        float4 acc = b4;
        #pragma unroll
        for (int h = 0; h < H; h++) {
            acc.x += w[h] * hv[h].x; acc.y += w[h] * hv[h].y;
            acc.z += w[h] * hv[h].z; acc.w += w[h] * hv[h].w;
        }
        long long oi = ((long long)s * S + t) * (long long)D + d4;
        if (oi + 3 < out_size) __stcs((float4*)(d_out + oi), acc);
    }
}

extern "C" void kernel_launch(void* const* d_in, const int* in_sizes, int n_in,
                              void* d_out, int out_size) {
    const float* x   = (const float*)d_in[0];
    const float* Wq  = (const float*)d_in[1];
    const float* bq  = (const float*)d_in[2];
    const float* Wk  = (const float*)d_in[3];
    const float* bk  = (const float*)d_in[4];
    const float* Wv  = (const float*)d_in[5];
    const float* bv  = (const float*)d_in[6];
    const float* Wqh = (const float*)d_in[7];
    // d_in[8] = bq_h, d_in[10] = bk_h
    const float* bqh = (const float*)d_in[8];
    const float* Wkh = (const float*)d_in[9];
    const float* Wvs = (const float*)d_in[11];
    const float* bvs = (const float*)d_in[12];
    const float* Wo  = (const float*)d_in[13];
    const float* bo  = (const float*)d_in[14];
    float* out = (float*)d_out;
    long long osz = (long long)out_size;

    k_pre_M    <<<dim3(H, 2, 2), 256>>>(Wqh, Wkh);
    k_pre_wvo  <<<dim3(8, 2),    256>>>(Wvs, Wo);
    k_pre_small<<<2,             512>>>(Wo, bvs, Wkh, bqh);
    k_qkv      <<<dim3(6, 8, 3), 256>>>(x, Wq, bq, Wk, bk, Wv, bv);
    k_qprime   <<<dim3(H, 6),    256>>>();
    k_hvo      <<<dim3(8, 48),   256>>>();
    k_bterm    <<<12,            256>>>();
    k_attn     <<<dim3(S, H),    128>>>(out, osz);
    k_comb     <<<dim3(S, 8),    128>>>(out, bo, osz);
}

// round 2
// speedup vs baseline: 1.8362x; 1.8362x over previous
#include <cuda_runtime.h>

#define S 384
#define D 512
#define H 8
#define DK 64
#define OUT_MAIN (S*S*D)   // 75497472

typedef unsigned long long ull;

// ---------------- packed f32x2 helpers (sm_100+) ----------------
__device__ __forceinline__ ull ffma2(ull a, ull b, ull c) {
    ull d;
    asm("fma.rn.f32x2 %0, %1, %2, %3;" : "=l"(d) : "l"(a), "l"(b), "l"(c));
    return d;
}
__device__ __forceinline__ ull pk2(float lo, float hi) {
    ull d; asm("mov.b64 %0, {%1, %2};" : "=l"(d) : "f"(lo), "f"(hi)); return d;
}
__device__ __forceinline__ float2 upk2(ull v) {
    float lo, hi; asm("mov.b64 {%0, %1}, %2;" : "=f"(lo), "=f"(hi) : "l"(v));
    return make_float2(lo, hi);
}

// ---------------- scratch ----------------
__device__ float g_q[S*D];
__device__ float g_k[S*D];
__device__ float g_v[S*D];
__device__ float g_M[H*DK*DK];       // Wq_h @ Wk_h^T
__device__ float g_Wvo[DK*D];        // Wv_s @ Wo
__device__ float g_bvo[D];           // bv_s @ Wo
__device__ float g_wh[H*DK];         // Wk_h @ bq_h
__device__ float g_qp[H*S*DK];       // qr @ M_h
__device__ float g_bt[H*S];          // kr . wh
__device__ float g_hvo3[S*(D/4)*H*4];// [t][d4][h][4], pre-scaled by 1/H
__device__ float g_attnT[S*S*H];     // [s][t][h]

// =================================================================
// K1: fused { qkv GEMMs (blocks 0..287) | M (288..319) | Wvo (320..383)
//             | bvo (384) | wh (385..388) }   128 threads
// =================================================================
__global__ __launch_bounds__(128) void K1(
    const float* __restrict__ x,
    const float* __restrict__ Wq, const float* __restrict__ bq,
    const float* __restrict__ Wk, const float* __restrict__ bk,
    const float* __restrict__ Wv, const float* __restrict__ bv,
    const float* __restrict__ Wqh, const float* __restrict__ Wkh,
    const float* __restrict__ Wvs, const float* __restrict__ bvs,
    const float* __restrict__ bqh, const float* __restrict__ Wo)
{
    __shared__ float sm[5392];
    int b = blockIdx.x;
    int tid = threadIdx.x;

    if (b < 288) {
        // ---- qkv: C[32m x 64n] tile, K=512, f32x2 packed ----
        int op = b / 96, r = b % 96;
        int m0 = (r % 12) * 32, n0 = (r / 12) * 64;
        const float* W; const float* bias; float* out;
        if (op == 0)      { W = Wq; bias = bq; out = g_q; }
        else if (op == 1) { W = Wk; bias = bk; out = g_k; }
        else              { W = Wv; bias = bv; out = g_v; }

        float* sA = sm;         // [16 k][33]: k*33 + m
        float* sB = sm + 528;   // [16 k][68]: k*68 + n

        int mm  = tid >> 2, kk4 = (tid & 3) * 4;
        int kb  = tid >> 4, nn4 = (tid & 15) * 4;
        int tm  = (tid >> 4) * 4, tn = (tid & 15) * 4;

        ull acc[4][2] = {};
        for (int k0 = 0; k0 < D; k0 += 16) {
            float4 a = *(const float4*)(x + (m0 + mm) * D + k0 + kk4);
            sA[(kk4+0)*33 + mm] = a.x; sA[(kk4+1)*33 + mm] = a.y;
            sA[(kk4+2)*33 + mm] = a.z; sA[(kk4+3)*33 + mm] = a.w;
            float4 b0 = *(const float4*)(W + (k0 + kb) * D + n0 + nn4);
            float4 b1 = *(const float4*)(W + (k0 + kb + 8) * D + n0 + nn4);
            *(float4*)&sB[kb*68 + nn4] = b0;
            *(float4*)&sB[(kb+8)*68 + nn4] = b1;
            __syncthreads();
            #pragma unroll
            for (int k2 = 0; k2 < 16; k2++) {
                float4 bvv = *(const float4*)&sB[k2*68 + tn];
                ull pb0 = pk2(bvv.x, bvv.y), pb1 = pk2(bvv.z, bvv.w);
                float av0 = sA[k2*33 + tm + 0];
                float av1 = sA[k2*33 + tm + 1];
                float av2 = sA[k2*33 + tm + 2];
                float av3 = sA[k2*33 + tm + 3];
                ull p0 = pk2(av0, av0), p1 = pk2(av1, av1);
                ull p2 = pk2(av2, av2), p3 = pk2(av3, av3);
                acc[0][0] = ffma2(p0, pb0, acc[0][0]); acc[0][1] = ffma2(p0, pb1, acc[0][1]);
                acc[1][0] = ffma2(p1, pb0, acc[1][0]); acc[1][1] = ffma2(p1, pb1, acc[1][1]);
                acc[2][0] = ffma2(p2, pb0, acc[2][0]); acc[2][1] = ffma2(p2, pb1, acc[2][1]);
                acc[3][0] = ffma2(p3, pb0, acc[3][0]); acc[3][1] = ffma2(p3, pb1, acc[3][1]);
            }
            __syncthreads();
        }
        float4 bias4 = *(const float4*)(bias + n0 + tn);
        #pragma unroll
        for (int i = 0; i < 4; i++) {
            float2 lo = upk2(acc[i][0]), hi = upk2(acc[i][1]);
            float4 o4 = make_float4(lo.x + bias4.x, lo.y + bias4.y,
                                    hi.x + bias4.z, hi.y + bias4.w);
            *(float4*)(out + (m0 + tm + i) * D + n0 + tn) = o4;
        }
    } else if (b < 320) {
        // ---- M_h tile: C[16i x 64j] = Wq_h[16,512] @ Wk_h[64,512]^T ----
        int p = b - 288;
        int h = p >> 2, i0 = (p & 3) * 16;
        float* sA = sm;          // [16][65]
        float* sB = sm + 1040;   // [64][65]
        int i = tid >> 3, jl = tid & 7;
        float acc[8] = {};
        for (int kc = 0; kc < 8; kc++) {
            int k0 = kc * 64;
            #pragma unroll
            for (int r2 = 0; r2 < 2; r2++) {
                int lin = (r2 * 128 + tid) * 4;
                int row = lin >> 6, col = lin & 63;
                float4 a4 = *(const float4*)(Wqh + (h*DK + i0 + row)*D + k0 + col);
                sA[row*65+col] = a4.x; sA[row*65+col+1] = a4.y;
                sA[row*65+col+2] = a4.z; sA[row*65+col+3] = a4.w;
            }
            #pragma unroll
            for (int r2 = 0; r2 < 8; r2++) {
                int lin = (r2 * 128 + tid) * 4;
                int row = lin >> 6, col = lin & 63;
                float4 b4 = *(const float4*)(Wkh + (h*DK + row)*D + k0 + col);
                sB[row*65+col] = b4.x; sB[row*65+col+1] = b4.y;
                sB[row*65+col+2] = b4.z; sB[row*65+col+3] = b4.w;
            }
            __syncthreads();
            #pragma unroll
            for (int kk = 0; kk < 64; kk++) {
                float a = sA[i*65 + kk];
                #pragma unroll
                for (int q = 0; q < 8; q++)
                    acc[q] += a * sB[(jl + 8*q)*65 + kk];
            }
            __syncthreads();
        }
        #pragma unroll
        for (int q = 0; q < 8; q++)
            g_M[h*DK*DK + (i0 + i)*DK + jl + 8*q] = acc[q];
    } else if (b < 384) {
        // ---- Wvo row m = b-320: Wvs[m,:] @ Wo ----
        int m = b - 320;
        float* sv = sm;
        *(float4*)&sv[tid*4] = *(const float4*)(Wvs + m*D + tid*4);
        __syncthreads();
        float acc0 = 0.f, acc1 = 0.f, acc2 = 0.f, acc3 = 0.f;
        #pragma unroll 4
        for (int k = 0; k < D; k++) {
            float4 w = *(const float4*)(Wo + k*D + tid*4);
            float a = sv[k];
            acc0 += a*w.x; acc1 += a*w.y; acc2 += a*w.z; acc3 += a*w.w;
        }
        *(float4*)(g_Wvo + m*D + tid*4) = make_float4(acc0, acc1, acc2, acc3);
    } else if (b == 384) {
        // ---- bvo = bvs @ Wo ----
        float* sv = sm;
        *(float4*)&sv[tid*4] = *(const float4*)(bvs + tid*4);
        __syncthreads();
        float acc0 = 0.f, acc1 = 0.f, acc2 = 0.f, acc3 = 0.f;
        #pragma unroll 4
        for (int k = 0; k < D; k++) {
            float4 w = *(const float4*)(Wo + k*D + tid*4);
            float a = sv[k];
            acc0 += a*w.x; acc1 += a*w.y; acc2 += a*w.z; acc3 += a*w.w;
        }
        *(float4*)(g_bvo + tid*4) = make_float4(acc0, acc1, acc2, acc3);
    } else {
        // ---- wh: 128 outputs per block, warp per 32 outputs ----
        int w = b - 385;               // 0..3
        int warp = tid >> 5, lane = tid & 31;
        for (int oi = 0; oi < 32; oi++) {
            int o = w*128 + warp*32 + oi;
            int hh = o >> 6, ii = o & 63;
            const float4* a4 = (const float4*)(Wkh + (hh*DK + ii)*D);
            const float4* b4p = (const float4*)(bqh + hh*D);
            float acc = 0.f;
            #pragma unroll
            for (int r2 = 0; r2 < 4; r2++) {
                float4 av = a4[lane + 32*r2], bv2 = b4p[lane + 32*r2];
                acc += av.x*bv2.x + av.y*bv2.y + av.z*bv2.z + av.w*bv2.w;
            }
            #pragma unroll
            for (int off = 16; off; off >>= 1)
                acc += __shfl_xor_sync(0xffffffffu, acc, off);
            if (lane == 0) g_wh[o] = acc;
        }
    }
}

// =================================================================
// K2: fused { qprime (0..47) | hvo (48..431) | bterm (432..443) }  256 thr
// =================================================================
__global__ __launch_bounds__(256) void K2() {
    __shared__ float sm[8320];
    int b = blockIdx.x;
    int tid = threadIdx.x;

    if (b < 48) {
        // ---- q' = qr @ M_h ----
        int h = b / 6, s0 = (b % 6) * 64;
        float* sM = sm;          // [64][65]
        float* sQ = sm + 4160;   // [64][65]
        #pragma unroll
        for (int r = 0; r < 4; r++) {
            int lin = tid * 4 + r * 1024;
            int row = lin >> 6, col = lin & 63;
            float4 m4 = *(const float4*)(g_M + h * DK * DK + lin);
            sM[row*65+col] = m4.x; sM[row*65+col+1] = m4.y;
            sM[row*65+col+2] = m4.z; sM[row*65+col+3] = m4.w;
            float4 q4 = *(const float4*)(g_q + (s0 + row) * D + h * DK + col);
            sQ[row*65+col] = q4.x; sQ[row*65+col+1] = q4.y;
            sQ[row*65+col+2] = q4.z; sQ[row*65+col+3] = q4.w;
        }
        __syncthreads();
        int sl = tid >> 2, jg = (tid & 3) * 16;
        float acc[16] = {};
        #pragma unroll
        for (int i = 0; i < 64; i++) {
            float qv = sQ[sl*65 + i];
            #pragma unroll
            for (int r = 0; r < 16; r++) acc[r] += qv * sM[i*65 + jg + r];
        }
        #pragma unroll
        for (int r = 0; r < 16; r++)
            g_qp[(h * S + s0 + sl) * DK + jg + r] = acc[r];
    } else if (b < 432) {
        // ---- hvo3[t][n/4][h][4] = (vr @ Wvo + bvo) * (1/H) ----
        int p = b - 48;
        int n0 = (p & 7) * 64;
        int q = p >> 3;
        int h = q / 6, t0 = (q % 6) * 64;
        float* sV = sm;          // [64][65]
        float* sW = sm + 4160;   // [64][65]
        #pragma unroll
        for (int r = 0; r < 4; r++) {
            int lin = tid * 4 + r * 1024;
            int row = lin >> 6, col = lin & 63;
            float4 v4 = *(const float4*)(g_v + (t0 + row) * D + h * DK + col);
            sV[row*65+col] = v4.x; sV[row*65+col+1] = v4.y;
            sV[row*65+col+2] = v4.z; sV[row*65+col+3] = v4.w;
            float4 w4 = *(const float4*)(g_Wvo + row * D + n0 + col);
            sW[row*65+col] = w4.x; sW[row*65+col+1] = w4.y;
            sW[row*65+col+2] = w4.z; sW[row*65+col+3] = w4.w;
        }
        __syncthreads();
        int tl = tid >> 2, ng = (tid & 3) * 16;
        float acc[16];
        #pragma unroll
        for (int r = 0; r < 16; r++) acc[r] = g_bvo[n0 + ng + r];
        #pragma unroll
        for (int i = 0; i < 64; i++) {
            float vv = sV[tl*65 + i];
            #pragma unroll
            for (int r = 0; r < 16; r++) acc[r] += vv * sW[i*65 + ng + r];
        }
        int t = t0 + tl;
        #pragma unroll
        for (int rq = 0; rq < 4; rq++) {
            int n = n0 + ng + rq * 4;
            float4 o4 = make_float4(acc[rq*4]*0.125f, acc[rq*4+1]*0.125f,
                                    acc[rq*4+2]*0.125f, acc[rq*4+3]*0.125f);
            *(float4*)(g_hvo3 + ((t * (D/4) + (n >> 2)) * H + h) * 4) = o4;
        }
    } else {
        // ---- bterm ----
        int id = (b - 432) * 256 + tid;     // < 3072
        int h = id / S, t = id % S;
        const float4* kp = (const float4*)(g_k + t * D + h * DK);
        const float4* wp = (const float4*)(g_wh + h * DK);
        float acc = 0.f;
        #pragma unroll
        for (int i = 0; i < 16; i++) {
            float4 k4 = kp[i], w4 = wp[i];
            acc += k4.x*w4.x + k4.y*w4.y + k4.z*w4.z + k4.w*w4.w;
        }
        g_bt[h * S + t] = acc;
    }
}

// =================================================================
// K3: scores + softmax. Block = (h, 32-s tile). 256 threads.
// thread: s = s0 + (tid>>3), owns t = (tid&7) + 8j per 64-t chunk.
// =================================================================
__global__ __launch_bounds__(256) void K3(float* __restrict__ d_out, long long osz) {
    __shared__ float sQ[32*68];
    __shared__ float sK[64*68];
    __shared__ float sBt[64];
    int h = blockIdx.x / 12;
    int s0 = (blockIdx.x % 12) * 32;
    int tid = threadIdx.x;
    int srow = tid >> 3, tl = tid & 7;

    #pragma unroll
    for (int r = 0; r < 2; r++) {
        int lin = (r * 256 + tid) * 4;
        int row = lin >> 6, col = lin & 63;
        *(float4*)&sQ[row*68 + col] =
            *(const float4*)(g_qp + (h * S + s0 + row) * DK + col);
    }

    float sc[48];
    for (int c = 0; c < 6; c++) {
        int t0c = c * 64;
        #pragma unroll
        for (int r = 0; r < 4; r++) {
            int lin = (r * 256 + tid) * 4;
            int row = lin >> 6, col = lin & 63;
            *(float4*)&sK[row*68 + col] =
                *(const float4*)(g_k + (t0c + row) * D + h * DK + col);
        }
        if (tid < 64) sBt[tid] = g_bt[h * S + t0c + tid];
        __syncthreads();
        #pragma unroll
        for (int j = 0; j < 8; j++) {
            int t2 = tl + 8 * j;
            float acc = 0.f;
            #pragma unroll
            for (int k4i = 0; k4i < 16; k4i++) {
                float4 q4 = *(const float4*)&sQ[srow*68 + k4i*4];
                float4 k4 = *(const float4*)&sK[t2*68 + k4i*4];
                acc += q4.x*k4.x + q4.y*k4.y + q4.z*k4.z + q4.w*k4.w;
            }
            sc[c*8 + j] = (acc + sBt[t2]) * 0.125f;
        }
        __syncthreads();
    }

    // softmax across the 8-lane t-groups (lanes differing in bits 0..2)
    float mx = -1e30f;
    #pragma unroll
    for (int i = 0; i < 48; i++) mx = fmaxf(mx, sc[i]);
    #pragma unroll
    for (int o = 1; o < 8; o <<= 1) mx = fmaxf(mx, __shfl_xor_sync(0xffffffffu, mx, o));
    float sum = 0.f;
    #pragma unroll
    for (int i = 0; i < 48; i++) { sc[i] = __expf(sc[i] - mx); sum += sc[i]; }
    #pragma unroll
    for (int o = 1; o < 8; o <<= 1) sum += __shfl_xor_sync(0xffffffffu, sum, o);
    float inv = 1.0f / sum;

    int s = s0 + srow;
    #pragma unroll
    for (int c = 0; c < 6; c++) {
        #pragma unroll
        for (int j = 0; j < 8; j++) {
            int t = c * 64 + tl + 8 * j;
            float a = sc[c*8 + j] * inv;
            g_attnT[((long long)s * S + t) * H + h] = a;
            if (h == H - 1) {
                long long oi = (long long)OUT_MAIN + (long long)s * S + t;
                if (oi < osz) d_out[oi] = a;
            }
        }
    }
}

// =================================================================
// K4: out[s,t,:] = bo + sum_h attnT[s,t,h] * hvo3[t,:,h]  (1/H folded)
// Block = (8-s tile, 48-t chunk). 256 threads: 128 d4 x 2 t-parity.
// =================================================================
__global__ __launch_bounds__(256) void K4(float* __restrict__ d_out,
                                          const float* __restrict__ bo,
                                          long long osz) {
    __shared__ float sAttn[8 * 392];
    int b = blockIdx.x;
    int s0 = (b >> 3) * 8, t0 = (b & 7) * 48;
    int tid = threadIdx.x;

    #pragma unroll
    for (int r = 0; r < 3; r++) {
        int lin = (r * 256 + tid) * 4;     // 0..3068
        int s = lin / 384, off = lin % 384;
        *(float4*)&sAttn[s * 392 + off] =
            *(const float4*)(g_attnT + ((long long)(s0 + s) * S + t0) * H + off);
    }
    __syncthreads();

    int d4 = (tid & 127) * 4;
    int tpar = tid >> 7;
    float4 b4 = *(const float4*)(bo + d4);

    for (int i = 0; i < 24; i++) {
        int tl = 2 * i + tpar;
        int t = t0 + tl;
        float4 hv[8];
        const float4* hp = (const float4*)(g_hvo3 + ((t * (D/4) + (d4 >> 2)) * H) * 4);
        #pragma unroll
        for (int h = 0; h < 8; h++) hv[h] = hp[h];
        #pragma unroll
        for (int s = 0; s < 8; s++) {
            float4 acc = b4;
            #pragma unroll
            for (int h = 0; h < 8; h++) {
                float w = sAttn[s * 392 + tl * 8 + h];
                acc.x += w * hv[h].x; acc.y += w * hv[h].y;
                acc.z += w * hv[h].z; acc.w += w * hv[h].w;
            }
            long long oi = ((long long)(s0 + s) * S + t) * D + d4;
            if (oi + 3 < osz) __stcs((float4*)(d_out + oi), acc);
        }
    }
}

extern "C" void kernel_launch(void* const* d_in, const int* in_sizes, int n_in,
                              void* d_out, int out_size) {
    const float* x   = (const float*)d_in[0];
    const float* Wq  = (const float*)d_in[1];
    const float* bq  = (const float*)d_in[2];
    const float* Wk  = (const float*)d_in[3];
    const float* bk  = (const float*)d_in[4];
    const float* Wv  = (const float*)d_in[5];
    const float* bv  = (const float*)d_in[6];
    const float* Wqh = (const float*)d_in[7];
    const float* bqh = (const float*)d_in[8];
    const float* Wkh = (const float*)d_in[9];
    const float* Wvs = (const float*)d_in[11];
    const float* bvs = (const float*)d_in[12];
    const float* Wo  = (const float*)d_in[13];
    const float* bo  = (const float*)d_in[14];
    float* out = (float*)d_out;
    long long osz = (long long)out_size;

    K1<<<389, 128>>>(x, Wq, bq, Wk, bk, Wv, bv, Wqh, Wkh, Wvs, bvs, bqh, Wo);
    K2<<<444, 256>>>();
    K3<<<96,  256>>>(out, osz);
    K4<<<384, 256>>>(out, bo, osz);
}

// round 3
// speedup vs baseline: 2.1458x; 1.1686x over previous
#include <cuda_runtime.h>

#define S 384
#define D 512
#define H 8
#define DK 64
#define OUT_MAIN (S*S*D)   // 75497472

typedef unsigned long long ull;

// ---------------- packed f32x2 helpers (sm_100+) ----------------
__device__ __forceinline__ ull ffma2(ull a, ull b, ull c) {
    ull d;
    asm("fma.rn.f32x2 %0, %1, %2, %3;" : "=l"(d) : "l"(a), "l"(b), "l"(c));
    return d;
}
__device__ __forceinline__ ull pk2(float lo, float hi) {
    ull d; asm("mov.b64 %0, {%1, %2};" : "=l"(d) : "f"(lo), "f"(hi)); return d;
}
__device__ __forceinline__ float2 upk2(ull v) {
    float lo, hi; asm("mov.b64 {%0, %1}, %2;" : "=f"(lo), "=f"(hi) : "l"(v));
    return make_float2(lo, hi);
}

// ---------------- scratch ----------------
__device__ float g_q[S*D];
__device__ float g_k[S*D];
__device__ float g_v[S*D];
__device__ float g_M[H*DK*DK];       // Wq_h @ Wk_h^T
__device__ float g_Wvo[DK*D];        // Wv_s @ Wo
__device__ float g_bvo[D];           // bv_s @ Wo
__device__ float g_wh[H*DK];         // Wk_h @ bq_h
__device__ float g_qp[H*S*DK];       // qr @ M_h
__device__ float g_bt[H*S];          // kr . wh
__device__ float g_hvo2[S*H*D];      // [t][h][d], pre-scaled by 1/H
__device__ float g_attnT[S*S*H];     // [s][t][h]

// =================================================================
// K1: fused { qkv GEMMs (0..287) | M (288..319) | Wvo (320..383)
//             | bvo (384) | wh (385..388) }   128 threads
// =================================================================
__global__ __launch_bounds__(128) void K1(
    const float* __restrict__ x,
    const float* __restrict__ Wq, const float* __restrict__ bq,
    const float* __restrict__ Wk, const float* __restrict__ bk,
    const float* __restrict__ Wv, const float* __restrict__ bv,
    const float* __restrict__ Wqh, const float* __restrict__ Wkh,
    const float* __restrict__ Wvs, const float* __restrict__ bvs,
    const float* __restrict__ bqh, const float* __restrict__ Wo)
{
    __shared__ float sm[5392];
    int b = blockIdx.x;
    int tid = threadIdx.x;

    if (b < 288) {
        int op = b / 96, r = b % 96;
        int m0 = (r % 12) * 32, n0 = (r / 12) * 64;
        const float* W; const float* bias; float* out;
        if (op == 0)      { W = Wq; bias = bq; out = g_q; }
        else if (op == 1) { W = Wk; bias = bk; out = g_k; }
        else              { W = Wv; bias = bv; out = g_v; }

        float* sA = sm;         // [16 k][33]
        float* sB = sm + 528;   // [16 k][68]

        int mm  = tid >> 2, kk4 = (tid & 3) * 4;
        int kb  = tid >> 4, nn4 = (tid & 15) * 4;
        int tm  = (tid >> 4) * 4, tn = (tid & 15) * 4;

        ull acc[4][2] = {};
        for (int k0 = 0; k0 < D; k0 += 16) {
            float4 a = *(const float4*)(x + (m0 + mm) * D + k0 + kk4);
            sA[(kk4+0)*33 + mm] = a.x; sA[(kk4+1)*33 + mm] = a.y;
            sA[(kk4+2)*33 + mm] = a.z; sA[(kk4+3)*33 + mm] = a.w;
            float4 b0 = *(const float4*)(W + (k0 + kb) * D + n0 + nn4);
            float4 b1 = *(const float4*)(W + (k0 + kb + 8) * D + n0 + nn4);
            *(float4*)&sB[kb*68 + nn4] = b0;
            *(float4*)&sB[(kb+8)*68 + nn4] = b1;
            __syncthreads();
            #pragma unroll
            for (int k2 = 0; k2 < 16; k2++) {
                float4 bvv = *(const float4*)&sB[k2*68 + tn];
                ull pb0 = pk2(bvv.x, bvv.y), pb1 = pk2(bvv.z, bvv.w);
                float av0 = sA[k2*33 + tm + 0];
                float av1 = sA[k2*33 + tm + 1];
                float av2 = sA[k2*33 + tm + 2];
                float av3 = sA[k2*33 + tm + 3];
                ull p0 = pk2(av0, av0), p1 = pk2(av1, av1);
                ull p2 = pk2(av2, av2), p3 = pk2(av3, av3);
                acc[0][0] = ffma2(p0, pb0, acc[0][0]); acc[0][1] = ffma2(p0, pb1, acc[0][1]);
                acc[1][0] = ffma2(p1, pb0, acc[1][0]); acc[1][1] = ffma2(p1, pb1, acc[1][1]);
                acc[2][0] = ffma2(p2, pb0, acc[2][0]); acc[2][1] = ffma2(p2, pb1, acc[2][1]);
                acc[3][0] = ffma2(p3, pb0, acc[3][0]); acc[3][1] = ffma2(p3, pb1, acc[3][1]);
            }
            __syncthreads();
        }
        float4 bias4 = *(const float4*)(bias + n0 + tn);
        #pragma unroll
        for (int i = 0; i < 4; i++) {
            float2 lo = upk2(acc[i][0]), hi = upk2(acc[i][1]);
            float4 o4 = make_float4(lo.x + bias4.x, lo.y + bias4.y,
                                    hi.x + bias4.z, hi.y + bias4.w);
            *(float4*)(out + (m0 + tm + i) * D + n0 + tn) = o4;
        }
    } else if (b < 320) {
        int p = b - 288;
        int h = p >> 2, i0 = (p & 3) * 16;
        float* sA = sm;          // [16][65]
        float* sB = sm + 1040;   // [64][65]
        int i = tid >> 3, jl = tid & 7;
        float acc[8] = {};
        for (int kc = 0; kc < 8; kc++) {
            int k0 = kc * 64;
            #pragma unroll
            for (int r2 = 0; r2 < 2; r2++) {
                int lin = (r2 * 128 + tid) * 4;
                int row = lin >> 6, col = lin & 63;
                float4 a4 = *(const float4*)(Wqh + (h*DK + i0 + row)*D + k0 + col);
                sA[row*65+col] = a4.x; sA[row*65+col+1] = a4.y;
                sA[row*65+col+2] = a4.z; sA[row*65+col+3] = a4.w;
            }
            #pragma unroll
            for (int r2 = 0; r2 < 8; r2++) {
                int lin = (r2 * 128 + tid) * 4;
                int row = lin >> 6, col = lin & 63;
                float4 b4 = *(const float4*)(Wkh + (h*DK + row)*D + k0 + col);
                sB[row*65+col] = b4.x; sB[row*65+col+1] = b4.y;
                sB[row*65+col+2] = b4.z; sB[row*65+col+3] = b4.w;
            }
            __syncthreads();
            #pragma unroll
            for (int kk = 0; kk < 64; kk++) {
                float a = sA[i*65 + kk];
                #pragma unroll
                for (int q = 0; q < 8; q++)
                    acc[q] += a * sB[(jl + 8*q)*65 + kk];
            }
            __syncthreads();
        }
        #pragma unroll
        for (int q = 0; q < 8; q++)
            g_M[h*DK*DK + (i0 + i)*DK + jl + 8*q] = acc[q];
    } else if (b < 384) {
        int m = b - 320;
        float* sv = sm;
        *(float4*)&sv[tid*4] = *(const float4*)(Wvs + m*D + tid*4);
        __syncthreads();
        float acc0 = 0.f, acc1 = 0.f, acc2 = 0.f, acc3 = 0.f;
        #pragma unroll 4
        for (int k = 0; k < D; k++) {
            float4 w = *(const float4*)(Wo + k*D + tid*4);
            float a = sv[k];
            acc0 += a*w.x; acc1 += a*w.y; acc2 += a*w.z; acc3 += a*w.w;
        }
        *(float4*)(g_Wvo + m*D + tid*4) = make_float4(acc0, acc1, acc2, acc3);
    } else if (b == 384) {
        float* sv = sm;
        *(float4*)&sv[tid*4] = *(const float4*)(bvs + tid*4);
        __syncthreads();
        float acc0 = 0.f, acc1 = 0.f, acc2 = 0.f, acc3 = 0.f;
        #pragma unroll 4
        for (int k = 0; k < D; k++) {
            float4 w = *(const float4*)(Wo + k*D + tid*4);
            float a = sv[k];
            acc0 += a*w.x; acc1 += a*w.y; acc2 += a*w.z; acc3 += a*w.w;
        }
        *(float4*)(g_bvo + tid*4) = make_float4(acc0, acc1, acc2, acc3);
    } else {
        int w = b - 385;
        int warp = tid >> 5, lane = tid & 31;
        for (int oi = 0; oi < 32; oi++) {
            int o = w*128 + warp*32 + oi;
            int hh = o >> 6, ii = o & 63;
            const float4* a4 = (const float4*)(Wkh + (hh*DK + ii)*D);
            const float4* b4p = (const float4*)(bqh + hh*D);
            float acc = 0.f;
            #pragma unroll
            for (int r2 = 0; r2 < 4; r2++) {
                float4 av = a4[lane + 32*r2], bv2 = b4p[lane + 32*r2];
                acc += av.x*bv2.x + av.y*bv2.y + av.z*bv2.z + av.w*bv2.w;
            }
            #pragma unroll
            for (int off = 16; off; off >>= 1)
                acc += __shfl_xor_sync(0xffffffffu, acc, off);
            if (lane == 0) g_wh[o] = acc;
        }
    }
}

// =================================================================
// K2: fused { qprime (0..47) | hvo (48..431) | bterm (432..443) }  256 thr
// =================================================================
__global__ __launch_bounds__(256) void K2() {
    __shared__ float sm[8320];
    int b = blockIdx.x;
    int tid = threadIdx.x;

    if (b < 48) {
        int h = b / 6, s0 = (b % 6) * 64;
        float* sM = sm;
        float* sQ = sm + 4160;
        #pragma unroll
        for (int r = 0; r < 4; r++) {
            int lin = tid * 4 + r * 1024;
            int row = lin >> 6, col = lin & 63;
            float4 m4 = *(const float4*)(g_M + h * DK * DK + lin);
            sM[row*65+col] = m4.x; sM[row*65+col+1] = m4.y;
            sM[row*65+col+2] = m4.z; sM[row*65+col+3] = m4.w;
            float4 q4 = *(const float4*)(g_q + (s0 + row) * D + h * DK + col);
            sQ[row*65+col] = q4.x; sQ[row*65+col+1] = q4.y;
            sQ[row*65+col+2] = q4.z; sQ[row*65+col+3] = q4.w;
        }
        __syncthreads();
        int sl = tid >> 2, jg = (tid & 3) * 16;
        float acc[16] = {};
        #pragma unroll
        for (int i = 0; i < 64; i++) {
            float qv = sQ[sl*65 + i];
            #pragma unroll
            for (int r = 0; r < 16; r++) acc[r] += qv * sM[i*65 + jg + r];
        }
        #pragma unroll
        for (int r = 0; r < 16; r++)
            g_qp[(h * S + s0 + sl) * DK + jg + r] = acc[r];
    } else if (b < 432) {
        int p = b - 48;
        int n0 = (p & 7) * 64;
        int q = p >> 3;
        int h = q / 6, t0 = (q % 6) * 64;
        float* sV = sm;
        float* sW = sm + 4160;
        #pragma unroll
        for (int r = 0; r < 4; r++) {
            int lin = tid * 4 + r * 1024;
            int row = lin >> 6, col = lin & 63;
            float4 v4 = *(const float4*)(g_v + (t0 + row) * D + h * DK + col);
            sV[row*65+col] = v4.x; sV[row*65+col+1] = v4.y;
            sV[row*65+col+2] = v4.z; sV[row*65+col+3] = v4.w;
            float4 w4 = *(const float4*)(g_Wvo + row * D + n0 + col);
            sW[row*65+col] = w4.x; sW[row*65+col+1] = w4.y;
            sW[row*65+col+2] = w4.z; sW[row*65+col+3] = w4.w;
        }
        __syncthreads();
        int tl = tid >> 2, ng = (tid & 3) * 16;
        float acc[16];
        #pragma unroll
        for (int r = 0; r < 16; r++) acc[r] = g_bvo[n0 + ng + r];
        #pragma unroll
        for (int i = 0; i < 64; i++) {
            float vv = sV[tl*65 + i];
            #pragma unroll
            for (int r = 0; r < 16; r++) acc[r] += vv * sW[i*65 + ng + r];
        }
        int t = t0 + tl;
        #pragma unroll
        for (int rq = 0; rq < 4; rq++) {
            int n = n0 + ng + rq * 4;
            float4 o4 = make_float4(acc[rq*4]*0.125f, acc[rq*4+1]*0.125f,
                                    acc[rq*4+2]*0.125f, acc[rq*4+3]*0.125f);
            *(float4*)(g_hvo2 + (t * H + h) * D + n) = o4;
        }
    } else {
        int id = (b - 432) * 256 + tid;
        int h = id / S, t = id % S;
        const float4* kp = (const float4*)(g_k + t * D + h * DK);
        const float4* wp = (const float4*)(g_wh + h * DK);
        float acc = 0.f;
        #pragma unroll
        for (int i = 0; i < 16; i++) {
            float4 k4 = kp[i], w4 = wp[i];
            acc += k4.x*w4.x + k4.y*w4.y + k4.z*w4.z + k4.w*w4.w;
        }
        g_bt[h * S + t] = acc;
    }
}

// =================================================================
// K3: scores + softmax. Block = (h, 16-s tile). 256 thr = 16 sg x 16 tg.
// Thread: 1 s row, 4 t per 64-t chunk (packed f32x2 over t-pairs).
// =================================================================
__global__ __launch_bounds__(256) void K3(float* __restrict__ d_out, long long osz) {
    __shared__ float sQ[16*68];
    __shared__ float sKT[64*68];   // transposed [k][t]
    __shared__ float sBt[64];
    int h = blockIdx.x / 24;
    int s0 = (blockIdx.x % 24) * 16;
    int tid = threadIdx.x;
    int sg = tid >> 4, tg = tid & 15;
    int s = s0 + sg;

    {   // load sQ: 16 rows x 64
        int lin = tid * 4;
        int row = lin >> 6, col = lin & 63;
        *(float4*)&sQ[row*68 + col] =
            *(const float4*)(g_qp + (h * S + s0 + row) * DK + col);
    }

    float sc[24];
    int tt = tid & 63, kg = tid >> 6;
    for (int c = 0; c < 6; c++) {
        __syncthreads();
        #pragma unroll
        for (int r = 0; r < 4; r++) {
            int k0 = kg * 16 + r * 4;
            float4 kv = *(const float4*)(g_k + (c*64 + tt) * D + h * DK + k0);
            sKT[(k0+0)*68 + tt] = kv.x;
            sKT[(k0+1)*68 + tt] = kv.y;
            sKT[(k0+2)*68 + tt] = kv.z;
            sKT[(k0+3)*68 + tt] = kv.w;
        }
        if (tid < 64) sBt[tid] = g_bt[h * S + c*64 + tid];
        __syncthreads();

        ull acc0 = 0, acc1 = 0;
        #pragma unroll
        for (int k4 = 0; k4 < 16; k4++) {
            float4 q4 = *(const float4*)&sQ[sg*68 + k4*4];
            float qa[4] = {q4.x, q4.y, q4.z, q4.w};
            #pragma unroll
            for (int kk = 0; kk < 4; kk++) {
                float4 kv = *(const float4*)&sKT[(k4*4+kk)*68 + tg*4];
                ull kA = pk2(kv.x, kv.y), kB = pk2(kv.z, kv.w);
                ull qp2 = pk2(qa[kk], qa[kk]);
                acc0 = ffma2(qp2, kA, acc0);
                acc1 = ffma2(qp2, kB, acc1);
            }
        }
        float2 v0 = upk2(acc0), v1 = upk2(acc1);
        int tb = tg * 4;
        sc[c*4+0] = (v0.x + sBt[tb+0]) * 0.125f;
        sc[c*4+1] = (v0.y + sBt[tb+1]) * 0.125f;
        sc[c*4+2] = (v1.x + sBt[tb+2]) * 0.125f;
        sc[c*4+3] = (v1.y + sBt[tb+3]) * 0.125f;
    }

    // softmax: row s spread over 16 tg lanes (lane bits 0..3)
    float mx = -1e30f;
    #pragma unroll
    for (int i = 0; i < 24; i++) mx = fmaxf(mx, sc[i]);
    #pragma unroll
    for (int o = 1; o < 16; o <<= 1) mx = fmaxf(mx, __shfl_xor_sync(0xffffffffu, mx, o));
    float sum = 0.f;
    #pragma unroll
    for (int i = 0; i < 24; i++) { sc[i] = __expf(sc[i] - mx); sum += sc[i]; }
    #pragma unroll
    for (int o = 1; o < 16; o <<= 1) sum += __shfl_xor_sync(0xffffffffu, sum, o);
    float inv = 1.0f / sum;

    #pragma unroll
    for (int c = 0; c < 6; c++) {
        #pragma unroll
        for (int j = 0; j < 4; j++) {
            int t = c*64 + tg*4 + j;
            float a = sc[c*4+j] * inv;
            g_attnT[((long long)s * S + t) * H + h] = a;
            if (h == H - 1) {
                long long oi = (long long)OUT_MAIN + (long long)s * S + t;
                if (oi < osz) d_out[oi] = a;
            }
        }
    }
}

// =================================================================
// K4: out[s,t,:] = bo + sum_h attnT[s,t,h] * hvo2[t,h,:]  (1/H folded)
// Block = (16-s, 24-t). 256 thr = 64 d8-lanes x 4 t-quarters. f32x2.
// =================================================================
__global__ __launch_bounds__(256) void K4(float* __restrict__ d_out,
                                          const float* __restrict__ bo,
                                          long long osz) {
    __shared__ float sW[16*24*8];   // [s][t][h]
    int b = blockIdx.x;
    int s0 = (b >> 4) * 16, t0 = (b & 15) * 24;
    int tid = threadIdx.x;

    #pragma unroll
    for (int r = 0; r < 3; r++) {
        int lin = r * 256 + tid;          // float4 index, 768 total
        int st = lin >> 1, half = lin & 1;
        int s = st / 24, t = st % 24;
        *(float4*)&sW[(s*24 + t)*8 + half*4] =
            *(const float4*)(g_attnT + ((long long)(s0+s)*S + (t0+t))*H + half*4);
    }
    __syncthreads();

    int dl = (tid & 63) * 8, tq = tid >> 6;
    float4 bA = *(const float4*)(bo + dl), bB = *(const float4*)(bo + dl + 4);
    ull bop[4] = {pk2(bA.x,bA.y), pk2(bA.z,bA.w), pk2(bB.x,bB.y), pk2(bB.z,bB.w)};

    for (int i = 0; i < 6; i++) {
        int tl = i * 4 + tq;
        int t = t0 + tl;
        ull hp[8][4];
        #pragma unroll
        for (int hh = 0; hh < 8; hh++) {
            const float* p = g_hvo2 + (t * H + hh) * D + dl;
            float4 a = *(const float4*)p;
            float4 c = *(const float4*)(p + 4);
            hp[hh][0] = pk2(a.x,a.y); hp[hh][1] = pk2(a.z,a.w);
            hp[hh][2] = pk2(c.x,c.y); hp[hh][3] = pk2(c.z,c.w);
        }
        #pragma unroll
        for (int s = 0; s < 16; s++) {
            const float* wb = &sW[(s*24 + tl)*8];
            float4 wa = *(const float4*)wb;
            float4 wc = *(const float4*)(wb + 4);
            ull w0 = pk2(wa.x,wa.x), w1 = pk2(wa.y,wa.y);
            ull w2 = pk2(wa.z,wa.z), w3 = pk2(wa.w,wa.w);
            ull w4 = pk2(wc.x,wc.x), w5 = pk2(wc.y,wc.y);
            ull w6 = pk2(wc.z,wc.z), w7 = pk2(wc.w,wc.w);
            ull acc0 = bop[0], acc1 = bop[1], acc2 = bop[2], acc3 = bop[3];
            acc0 = ffma2(w0, hp[0][0], acc0); acc1 = ffma2(w0, hp[0][1], acc1);
            acc2 = ffma2(w0, hp[0][2], acc2); acc3 = ffma2(w0, hp[0][3], acc3);
            acc0 = ffma2(w1, hp[1][0], acc0); acc1 = ffma2(w1, hp[1][1], acc1);
            acc2 = ffma2(w1, hp[1][2], acc2); acc3 = ffma2(w1, hp[1][3], acc3);
            acc0 = ffma2(w2, hp[2][0], acc0); acc1 = ffma2(w2, hp[2][1], acc1);
            acc2 = ffma2(w2, hp[2][2], acc2); acc3 = ffma2(w2, hp[2][3], acc3);
            acc0 = ffma2(w3, hp[3][0], acc0); acc1 = ffma2(w3, hp[3][1], acc1);
            acc2 = ffma2(w3, hp[3][2], acc2); acc3 = ffma2(w3, hp[3][3], acc3);
            acc0 = ffma2(w4, hp[4][0], acc0); acc1 = ffma2(w4, hp[4][1], acc1);
            acc2 = ffma2(w4, hp[4][2], acc2); acc3 = ffma2(w4, hp[4][3], acc3);
            acc0 = ffma2(w5, hp[5][0], acc0); acc1 = ffma2(w5, hp[5][1], acc1);
            acc2 = ffma2(w5, hp[5][2], acc2); acc3 = ffma2(w5, hp[5][3], acc3);
            acc0 = ffma2(w6, hp[6][0], acc0); acc1 = ffma2(w6, hp[6][1], acc1);
            acc2 = ffma2(w6, hp[6][2], acc2); acc3 = ffma2(w6, hp[6][3], acc3);
            acc0 = ffma2(w7, hp[7][0], acc0); acc1 = ffma2(w7, hp[7][1], acc1);
            acc2 = ffma2(w7, hp[7][2], acc2); acc3 = ffma2(w7, hp[7][3], acc3);
            float2 r0 = upk2(acc0), r1 = upk2(acc1);
            float2 r2 = upk2(acc2), r3 = upk2(acc3);
            long long oi = ((long long)(s0 + s) * S + t) * D + dl;
            if (oi + 7 < osz) {
                __stcs((float4*)(d_out + oi),     make_float4(r0.x,r0.y,r1.x,r1.y));
                __stcs((float4*)(d_out + oi + 4), make_float4(r2.x,r2.y,r3.x,r3.y));
            }
        }
    }
}

extern "C" void kernel_launch(void* const* d_in, const int* in_sizes, int n_in,
                              void* d_out, int out_size) {
    const float* x   = (const float*)d_in[0];
    const float* Wq  = (const float*)d_in[1];
    const float* bq  = (const float*)d_in[2];
    const float* Wk  = (const float*)d_in[3];
    const float* bk  = (const float*)d_in[4];
    const float* Wv  = (const float*)d_in[5];
    const float* bv  = (const float*)d_in[6];
    const float* Wqh = (const float*)d_in[7];
    const float* bqh = (const float*)d_in[8];
    const float* Wkh = (const float*)d_in[9];
    const float* Wvs = (const float*)d_in[11];
    const float* bvs = (const float*)d_in[12];
    const float* Wo  = (const float*)d_in[13];
    const float* bo  = (const float*)d_in[14];
    float* out = (float*)d_out;
    long long osz = (long long)out_size;

    K1<<<389, 128>>>(x, Wq, bq, Wk, bk, Wv, bv, Wqh, Wkh, Wvs, bvs, bqh, Wo);
    K2<<<444, 256>>>();
    K3<<<192, 256>>>(out, osz);
    K4<<<384, 256>>>(out, bo, osz);
}

// round 5
// speedup vs baseline: 2.2530x; 1.0500x over previous
#include <cuda_runtime.h>

#define S 384
#define D 512
#define H 8
#define DK 64
#define OUT_MAIN (S*S*D)   // 75497472

typedef unsigned long long ull;

__device__ __forceinline__ ull ffma2(ull a, ull b, ull c) {
    ull d;
    asm("fma.rn.f32x2 %0, %1, %2, %3;" : "=l"(d) : "l"(a), "l"(b), "l"(c));
    return d;
}
__device__ __forceinline__ ull pk2(float lo, float hi) {
    ull d; asm("mov.b64 %0, {%1, %2};" : "=l"(d) : "f"(lo), "f"(hi)); return d;
}
__device__ __forceinline__ float2 upk2(ull v) {
    float lo, hi; asm("mov.b64 {%0, %1}, %2;" : "=f"(lo), "=f"(hi) : "l"(v));
    return make_float2(lo, hi);
}

// ---------------- scratch ----------------
__device__ float g_q[S*D];
__device__ float g_k[S*D];
__device__ float g_v[S*D];
__device__ float g_M[H*DK*DK];       // Wq_h @ Wk_h^T
__device__ float g_Wvo[DK*D];        // Wv_s @ Wo
__device__ float g_bvo[D];           // bv_s @ Wo
__device__ float g_wh[H*DK];         // Wk_h @ bq_h
__device__ float g_hvo2[S*H*D];      // [t][h][d], pre-scaled by 1/H
__device__ float g_attnT[S*S*H];     // [s][t][h]

// =================================================================
// K1: fused { qkv GEMMs (0..287) | M (288..319) | Wvo (320..383)
//             | bvo (384) | wh (385..388) }   128 threads
// =================================================================
__global__ __launch_bounds__(128) void K1(
    const float* __restrict__ x,
    const float* __restrict__ Wq, const float* __restrict__ bq,
    const float* __restrict__ Wk, const float* __restrict__ bk,
    const float* __restrict__ Wv, const float* __restrict__ bv,
    const float* __restrict__ Wqh, const float* __restrict__ Wkh,
    const float* __restrict__ Wvs, const float* __restrict__ bvs,
    const float* __restrict__ bqh, const float* __restrict__ Wo)
{
    __shared__ float sm[5392];
    int b = blockIdx.x;
    int tid = threadIdx.x;

    if (b < 288) {
        int op = b / 96, r = b % 96;
        int m0 = (r % 12) * 32, n0 = (r / 12) * 64;
        const float* W; const float* bias; float* out;
        if (op == 0)      { W = Wq; bias = bq; out = g_q; }
        else if (op == 1) { W = Wk; bias = bk; out = g_k; }
        else              { W = Wv; bias = bv; out = g_v; }

        float* sA = sm;         // [16 k][33]
        float* sB = sm + 528;   // [16 k][68]

        int mm  = tid >> 2, kk4 = (tid & 3) * 4;
        int kb  = tid >> 4, nn4 = (tid & 15) * 4;
        int tm  = (tid >> 4) * 4, tn = (tid & 15) * 4;

        ull acc[4][2] = {};
        for (int k0 = 0; k0 < D; k0 += 16) {
            float4 a = *(const float4*)(x + (m0 + mm) * D + k0 + kk4);
            sA[(kk4+0)*33 + mm] = a.x; sA[(kk4+1)*33 + mm] = a.y;
            sA[(kk4+2)*33 + mm] = a.z; sA[(kk4+3)*33 + mm] = a.w;
            float4 b0 = *(const float4*)(W + (k0 + kb) * D + n0 + nn4);
            float4 b1 = *(const float4*)(W + (k0 + kb + 8) * D + n0 + nn4);
            *(float4*)&sB[kb*68 + nn4] = b0;
            *(float4*)&sB[(kb+8)*68 + nn4] = b1;
            __syncthreads();
            #pragma unroll
            for (int k2 = 0; k2 < 16; k2++) {
                float4 bvv = *(const float4*)&sB[k2*68 + tn];
                ull pb0 = pk2(bvv.x, bvv.y), pb1 = pk2(bvv.z, bvv.w);
                float av0 = sA[k2*33 + tm + 0];
                float av1 = sA[k2*33 + tm + 1];
                float av2 = sA[k2*33 + tm + 2];
                float av3 = sA[k2*33 + tm + 3];
                ull p0 = pk2(av0, av0), p1 = pk2(av1, av1);
                ull p2 = pk2(av2, av2), p3 = pk2(av3, av3);
                acc[0][0] = ffma2(p0, pb0, acc[0][0]); acc[0][1] = ffma2(p0, pb1, acc[0][1]);
                acc[1][0] = ffma2(p1, pb0, acc[1][0]); acc[1][1] = ffma2(p1, pb1, acc[1][1]);
                acc[2][0] = ffma2(p2, pb0, acc[2][0]); acc[2][1] = ffma2(p2, pb1, acc[2][1]);
                acc[3][0] = ffma2(p3, pb0, acc[3][0]); acc[3][1] = ffma2(p3, pb1, acc[3][1]);
            }
            __syncthreads();
        }
        float4 bias4 = *(const float4*)(bias + n0 + tn);
        #pragma unroll
        for (int i = 0; i < 4; i++) {
            float2 lo = upk2(acc[i][0]), hi = upk2(acc[i][1]);
            float4 o4 = make_float4(lo.x + bias4.x, lo.y + bias4.y,
                                    hi.x + bias4.z, hi.y + bias4.w);
            *(float4*)(out + (m0 + tm + i) * D + n0 + tn) = o4;
        }
    } else if (b < 320) {
        int p = b - 288;
        int h = p >> 2, i0 = (p & 3) * 16;
        float* sA = sm;          // [16][65]
        float* sB = sm + 1040;   // [64][65]
        int i = tid >> 3, jl = tid & 7;
        float acc[8] = {};
        for (int kc = 0; kc < 8; kc++) {
            int k0 = kc * 64;
            #pragma unroll
            for (int r2 = 0; r2 < 2; r2++) {
                int lin = (r2 * 128 + tid) * 4;
                int row = lin >> 6, col = lin & 63;
                float4 a4 = *(const float4*)(Wqh + (h*DK + i0 + row)*D + k0 + col);
                sA[row*65+col] = a4.x; sA[row*65+col+1] = a4.y;
                sA[row*65+col+2] = a4.z; sA[row*65+col+3] = a4.w;
            }
            #pragma unroll
            for (int r2 = 0; r2 < 8; r2++) {
                int lin = (r2 * 128 + tid) * 4;
                int row = lin >> 6, col = lin & 63;
                float4 b4 = *(const float4*)(Wkh + (h*DK + row)*D + k0 + col);
                sB[row*65+col] = b4.x; sB[row*65+col+1] = b4.y;
                sB[row*65+col+2] = b4.z; sB[row*65+col+3] = b4.w;
            }
            __syncthreads();
            #pragma unroll
            for (int kk = 0; kk < 64; kk++) {
                float a = sA[i*65 + kk];
                #pragma unroll
                for (int q = 0; q < 8; q++)
                    acc[q] += a * sB[(jl + 8*q)*65 + kk];
            }
            __syncthreads();
        }
        #pragma unroll
        for (int q = 0; q < 8; q++)
            g_M[h*DK*DK + (i0 + i)*DK + jl + 8*q] = acc[q];
    } else if (b < 384) {
        int m = b - 320;
        float* sv = sm;
        *(float4*)&sv[tid*4] = *(const float4*)(Wvs + m*D + tid*4);
        __syncthreads();
        float acc0 = 0.f, acc1 = 0.f, acc2 = 0.f, acc3 = 0.f;
        #pragma unroll 4
        for (int k = 0; k < D; k++) {
            float4 w = *(const float4*)(Wo + k*D + tid*4);
            float a = sv[k];
            acc0 += a*w.x; acc1 += a*w.y; acc2 += a*w.z; acc3 += a*w.w;
        }
        *(float4*)(g_Wvo + m*D + tid*4) = make_float4(acc0, acc1, acc2, acc3);
    } else if (b == 384) {
        float* sv = sm;
        *(float4*)&sv[tid*4] = *(const float4*)(bvs + tid*4);
        __syncthreads();
        float acc0 = 0.f, acc1 = 0.f, acc2 = 0.f, acc3 = 0.f;
        #pragma unroll 4
        for (int k = 0; k < D; k++) {
            float4 w = *(const float4*)(Wo + k*D + tid*4);
            float a = sv[k];
            acc0 += a*w.x; acc1 += a*w.y; acc2 += a*w.z; acc3 += a*w.w;
        }
        *(float4*)(g_bvo + tid*4) = make_float4(acc0, acc1, acc2, acc3);
    } else {
        int w = b - 385;
        int warp = tid >> 5, lane = tid & 31;
        for (int oi = 0; oi < 32; oi++) {
            int o = w*128 + warp*32 + oi;
            int hh = o >> 6, ii = o & 63;
            const float4* a4 = (const float4*)(Wkh + (hh*DK + ii)*D);
            const float4* b4p = (const float4*)(bqh + hh*D);
            float acc = 0.f;
            #pragma unroll
            for (int r2 = 0; r2 < 4; r2++) {
                float4 av = a4[lane + 32*r2], bv2 = b4p[lane + 32*r2];
                acc += av.x*bv2.x + av.y*bv2.y + av.z*bv2.z + av.w*bv2.w;
            }
            #pragma unroll
            for (int off = 16; off; off >>= 1)
                acc += __shfl_xor_sync(0xffffffffu, acc, off);
            if (lane == 0) g_wh[o] = acc;
        }
    }
}

// =================================================================
// K2: fused { attn+softmax with inline qprime/bterm (0..191)
//             | hvo (192..575) }   256 threads
// =================================================================
__global__ __launch_bounds__(256) void K2(float* __restrict__ d_out, long long osz) {
    __shared__ float sm[8512];
    int b = blockIdx.x;
    int tid = threadIdx.x;

    if (b < 192) {
        // ---- attention rows: head h, s-tile of 16 ----
        int h = b / 24;
        int s0 = (b % 24) * 16;
        float* sKT = sm;             // [64][68]  (also holds M in prologue)
        float* sQp = sm + 4352;      // [16][68]
        float* sQ  = sm + 5440;      // [16][65]
        float* swh = sm + 6480;      // [64]
        float* sBt = sm + 6544;      // [64]

        // prologue: load M into sKT, q rows into sQ, wh
        #pragma unroll
        for (int r = 0; r < 4; r++) {
            int lin = (r * 256 + tid) * 4;
            int row = lin >> 6, col = lin & 63;
            float4 m4 = *(const float4*)(g_M + h * DK * DK + lin);
            sKT[row*68+col] = m4.x; sKT[row*68+col+1] = m4.y;
            sKT[row*68+col+2] = m4.z; sKT[row*68+col+3] = m4.w;
        }
        {
            int lin = tid * 4;
            int row = lin >> 6, col = lin & 63;
            float4 q4 = *(const float4*)(g_q + (s0 + row) * D + h * DK + col);
            sQ[row*65+col] = q4.x; sQ[row*65+col+1] = q4.y;
            sQ[row*65+col+2] = q4.z; sQ[row*65+col+3] = q4.w;
        }
        if (tid < 64) swh[tid] = g_wh[h * DK + tid];
        __syncthreads();

        // qp[sg][jg..jg+3] = sum_i q[sg][i] * M[i][jg..]
        {
            int sgq = tid >> 4, jg = (tid & 15) * 4;
            float a0 = 0.f, a1 = 0.f, a2 = 0.f, a3 = 0.f;
            #pragma unroll
            for (int i = 0; i < 64; i++) {
                float qv = sQ[sgq*65 + i];
                float4 m4 = *(const float4*)&sKT[i*68 + jg];
                a0 += qv*m4.x; a1 += qv*m4.y; a2 += qv*m4.z; a3 += qv*m4.w;
            }
            __syncthreads();   // all M reads done before sKT reuse
            sQp[sgq*68 + jg+0] = a0; sQp[sgq*68 + jg+1] = a1;
            sQp[sgq*68 + jg+2] = a2; sQp[sgq*68 + jg+3] = a3;
        }
        __syncthreads();

        int sg = tid >> 4, tg = tid & 15;
        int s = s0 + sg;
        int tt = tid & 63, kg = tid >> 6;

        float sc[24];
        for (int c = 0; c < 6; c++) {
            // load K chunk transposed [k][t]
            #pragma unroll
            for (int r = 0; r < 4; r++) {
                int k0 = kg * 16 + r * 4;
                float4 kv = *(const float4*)(g_k + (c*64 + tt) * D + h * DK + k0);
                sKT[(k0+0)*68 + tt] = kv.x;
                sKT[(k0+1)*68 + tt] = kv.y;
                sKT[(k0+2)*68 + tt] = kv.z;
                sKT[(k0+3)*68 + tt] = kv.w;
            }
            __syncthreads();
            // bterm for this chunk
            if (tid < 64) {
                float bt = 0.f;
                #pragma unroll
                for (int k = 0; k < 64; k++) bt += sKT[k*68 + tid] * swh[k];
                sBt[tid] = bt;
            }
            // scores
            ull acc0 = 0, acc1 = 0;
            #pragma unroll
            for (int k4 = 0; k4 < 16; k4++) {
                float4 q4 = *(const float4*)&sQp[sg*68 + k4*4];
                float qa[4] = {q4.x, q4.y, q4.z, q4.w};
                #pragma unroll
                for (int kk = 0; kk < 4; kk++) {
                    float4 kv = *(const float4*)&sKT[(k4*4+kk)*68 + tg*4];
                    ull kA = pk2(kv.x, kv.y), kB = pk2(kv.z, kv.w);
                    ull qp2 = pk2(qa[kk], qa[kk]);
                    acc0 = ffma2(qp2, kA, acc0);
                    acc1 = ffma2(qp2, kB, acc1);
                }
            }
            __syncthreads();   // sBt ready; also gates next chunk's sKT overwrite
            float2 v0 = upk2(acc0), v1 = upk2(acc1);
            int tb = tg * 4;
            sc[c*4+0] = (v0.x + sBt[tb+0]) * 0.125f;
            sc[c*4+1] = (v0.y + sBt[tb+1]) * 0.125f;
            sc[c*4+2] = (v1.x + sBt[tb+2]) * 0.125f;
            sc[c*4+3] = (v1.y + sBt[tb+3]) * 0.125f;
        }

        float mx = -1e30f;
        #pragma unroll
        for (int i = 0; i < 24; i++) mx = fmaxf(mx, sc[i]);
        #pragma unroll
        for (int o = 1; o < 16; o <<= 1) mx = fmaxf(mx, __shfl_xor_sync(0xffffffffu, mx, o));
        float sum = 0.f;
        #pragma unroll
        for (int i = 0; i < 24; i++) { sc[i] = __expf(sc[i] - mx); sum += sc[i]; }
        #pragma unroll
        for (int o = 1; o < 16; o <<= 1) sum += __shfl_xor_sync(0xffffffffu, sum, o);
        float inv = 1.0f / sum;

        #pragma unroll
        for (int c = 0; c < 6; c++) {
            #pragma unroll
            for (int j = 0; j < 4; j++) {
                int t = c*64 + tg*4 + j;
                float a = sc[c*4+j] * inv;
                g_attnT[((long long)s * S + t) * H + h] = a;
                if (h == H - 1) {
                    long long oi = (long long)OUT_MAIN + (long long)s * S + t;
                    if (oi < osz) d_out[oi] = a;
                }
            }
        }
    } else {
        // ---- hvo2[t][h][:] = (vr @ Wvo + bvo) * (1/H) ----
        int p = b - 192;
        int n0 = (p & 7) * 64;
        int q = p >> 3;
        int h = q / 6, t0 = (q % 6) * 64;
        float* sV = sm;          // [64][65]
        float* sW = sm + 4160;   // [64][68]  (stride 68 -> 16B-aligned float4 rows)
        #pragma unroll
        for (int r = 0; r < 4; r++) {
            int lin = tid * 4 + r * 1024;
            int row = lin >> 6, col = lin & 63;
            float4 v4 = *(const float4*)(g_v + (t0 + row) * D + h * DK + col);
            sV[row*65+col] = v4.x; sV[row*65+col+1] = v4.y;
            sV[row*65+col+2] = v4.z; sV[row*65+col+3] = v4.w;
            float4 w4 = *(const float4*)(g_Wvo + row * D + n0 + col);
            *(float4*)&sW[row*68+col] = w4;
        }
        __syncthreads();
        int tl = tid >> 2, ng = (tid & 3) * 16;
        ull acc[8];
        {
            float4 b0 = *(const float4*)(g_bvo + n0 + ng);
            float4 b1 = *(const float4*)(g_bvo + n0 + ng + 4);
            float4 b2 = *(const float4*)(g_bvo + n0 + ng + 8);
            float4 b3 = *(const float4*)(g_bvo + n0 + ng + 12);
            acc[0] = pk2(b0.x,b0.y); acc[1] = pk2(b0.z,b0.w);
            acc[2] = pk2(b1.x,b1.y); acc[3] = pk2(b1.z,b1.w);
            acc[4] = pk2(b2.x,b2.y); acc[5] = pk2(b2.z,b2.w);
            acc[6] = pk2(b3.x,b3.y); acc[7] = pk2(b3.z,b3.w);
        }
        #pragma unroll
        for (int i = 0; i < 64; i++) {
            float vv = sV[tl*65 + i];
            ull vp = pk2(vv, vv);
            const float* wr = &sW[i*68 + ng];
            float4 w0 = *(const float4*)wr;
            float4 w1 = *(const float4*)(wr + 4);
            float4 w2 = *(const float4*)(wr + 8);
            float4 w3 = *(const float4*)(wr + 12);
            acc[0] = ffma2(vp, pk2(w0.x,w0.y), acc[0]);
            acc[1] = ffma2(vp, pk2(w0.z,w0.w), acc[1]);
            acc[2] = ffma2(vp, pk2(w1.x,w1.y), acc[2]);
            acc[3] = ffma2(vp, pk2(w1.z,w1.w), acc[3]);
            acc[4] = ffma2(vp, pk2(w2.x,w2.y), acc[4]);
            acc[5] = ffma2(vp, pk2(w2.z,w2.w), acc[5]);
            acc[6] = ffma2(vp, pk2(w3.x,w3.y), acc[6]);
            acc[7] = ffma2(vp, pk2(w3.z,w3.w), acc[7]);
        }
        int t = t0 + tl;
        #pragma unroll
        for (int rq = 0; rq < 4; rq++) {
            float2 lo = upk2(acc[rq*2]), hi = upk2(acc[rq*2+1]);
            float4 o4 = make_float4(lo.x*0.125f, lo.y*0.125f,
                                    hi.x*0.125f, hi.y*0.125f);
            *(float4*)(g_hvo2 + (t * H + h) * D + n0 + ng + rq*4) = o4;
        }
    }
}

// =================================================================
// K4: out[s,t,:] = bo + sum_h attnT[s,t,h] * hvo2[t,h,:]  (1/H folded)
// Block = (32-s, 12-t). 256 thr = 64 d8-lanes x 4 t-quarters. f32x2.
// =================================================================
__global__ __launch_bounds__(256) void K4(float* __restrict__ d_out,
                                          const float* __restrict__ bo,
                                          long long osz) {
    __shared__ float sW[32*12*8];   // [s][t][h]
    int b = blockIdx.x;
    int s0 = (b % 12) * 32, t0 = (b / 12) * 12;
    int tid = threadIdx.x;

    #pragma unroll
    for (int r = 0; r < 3; r++) {
        int lin = r * 256 + tid;          // float4 index, 768 total
        int st = lin >> 1, half = lin & 1;
        int s = st / 12, t = st % 12;
        *(float4*)&sW[(s*12 + t)*8 + half*4] =
            *(const float4*)(g_attnT + ((long long)(s0+s)*S + (t0+t))*H + half*4);
    }
    __syncthreads();

    int dl = (tid & 63) * 8, tq = tid >> 6;
    float4 bA = *(const float4*)(bo + dl), bB = *(const float4*)(bo + dl + 4);
    ull bop[4] = {pk2(bA.x,bA.y), pk2(bA.z,bA.w), pk2(bB.x,bB.y), pk2(bB.z,bB.w)};

    for (int i = 0; i < 3; i++) {
        int tl = i * 4 + tq;
        int t = t0 + tl;
        ull hp[8][4];
        #pragma unroll
        for (int hh = 0; hh < 8; hh++) {
            const float* p = g_hvo2 + (t * H + hh) * D + dl;
            float4 a = *(const float4*)p;
            float4 c = *(const float4*)(p + 4);
            hp[hh][0] = pk2(a.x,a.y); hp[hh][1] = pk2(a.z,a.w);
            hp[hh][2] = pk2(c.x,c.y); hp[hh][3] = pk2(c.z,c.w);
        }
        #pragma unroll
        for (int s = 0; s < 32; s++) {
            const float* wb = &sW[(s*12 + tl)*8];
            float4 wa = *(const float4*)wb;
            float4 wc = *(const float4*)(wb + 4);
            ull w0 = pk2(wa.x,wa.x), w1 = pk2(wa.y,wa.y);
            ull w2 = pk2(wa.z,wa.z), w3 = pk2(wa.w,wa.w);
            ull w4 = pk2(wc.x,wc.x), w5 = pk2(wc.y,wc.y);
            ull w6 = pk2(wc.z,wc.z), w7 = pk2(wc.w,wc.w);
            ull acc0 = bop[0], acc1 = bop[1], acc2 = bop[2], acc3 = bop[3];
            acc0 = ffma2(w0, hp[0][0], acc0); acc1 = ffma2(w0, hp[0][1], acc1);
            acc2 = ffma2(w0, hp[0][2], acc2); acc3 = ffma2(w0, hp[0][3], acc3);
            acc0 = ffma2(w1, hp[1][0], acc0); acc1 = ffma2(w1, hp[1][1], acc1);
            acc2 = ffma2(w1, hp[1][2], acc2); acc3 = ffma2(w1, hp[1][3], acc3);
            acc0 = ffma2(w2, hp[2][0], acc0); acc1 = ffma2(w2, hp[2][1], acc1);
            acc2 = ffma2(w2, hp[2][2], acc2); acc3 = ffma2(w2, hp[2][3], acc3);
            acc0 = ffma2(w3, hp[3][0], acc0); acc1 = ffma2(w3, hp[3][1], acc1);
            acc2 = ffma2(w3, hp[3][2], acc2); acc3 = ffma2(w3, hp[3][3], acc3);
            acc0 = ffma2(w4, hp[4][0], acc0); acc1 = ffma2(w4, hp[4][1], acc1);
            acc2 = ffma2(w4, hp[4][2], acc2); acc3 = ffma2(w4, hp[4][3], acc3);
            acc0 = ffma2(w5, hp[5][0], acc0); acc1 = ffma2(w5, hp[5][1], acc1);
            acc2 = ffma2(w5, hp[5][2], acc2); acc3 = ffma2(w5, hp[5][3], acc3);
            acc0 = ffma2(w6, hp[6][0], acc0); acc1 = ffma2(w6, hp[6][1], acc1);
            acc2 = ffma2(w6, hp[6][2], acc2); acc3 = ffma2(w6, hp[6][3], acc3);
            acc0 = ffma2(w7, hp[7][0], acc0); acc1 = ffma2(w7, hp[7][1], acc1);
            acc2 = ffma2(w7, hp[7][2], acc2); acc3 = ffma2(w7, hp[7][3], acc3);
            float2 r0 = upk2(acc0), r1 = upk2(acc1);
            float2 r2 = upk2(acc2), r3 = upk2(acc3);
            long long oi = ((long long)(s0 + s) * S + t) * D + dl;
            if (oi + 7 < osz) {
                __stcs((float4*)(d_out + oi),     make_float4(r0.x,r0.y,r1.x,r1.y));
                __stcs((float4*)(d_out + oi + 4), make_float4(r2.x,r2.y,r3.x,r3.y));
            }
        }
    }
}

extern "C" void kernel_launch(void* const* d_in, const int* in_sizes, int n_in,
                              void* d_out, int out_size) {
    const float* x   = (const float*)d_in[0];
    const float* Wq  = (const float*)d_in[1];
    const float* bq  = (const float*)d_in[2];
    const float* Wk  = (const float*)d_in[3];
    const float* bk  = (const float*)d_in[4];
    const float* Wv  = (const float*)d_in[5];
    const float* bv  = (const float*)d_in[6];
    const float* Wqh = (const float*)d_in[7];
    const float* bqh = (const float*)d_in[8];
    const float* Wkh = (const float*)d_in[9];
    const float* Wvs = (const float*)d_in[11];
    const float* bvs = (const float*)d_in[12];
    const float* Wo  = (const float*)d_in[13];
    const float* bo  = (const float*)d_in[14];
    float* out = (float*)d_out;
    long long osz = (long long)out_size;

    K1<<<389, 128>>>(x, Wq, bq, Wk, bk, Wv, bv, Wqh, Wkh, Wvs, bvs, bqh, Wo);
    K2<<<576, 256>>>(out, osz);
    K4<<<384, 256>>>(out, bo, osz);
}